// round 13
// baseline (speedup 1.0000x reference)
#include <cuda_runtime.h>
#include <cuda_fp16.h>
#include <mma.h>

using namespace nvcuda;

#define N_NODES 100000
#define N_EDGES 1600000
#define D 128
#define NEG_SLOPE 0.01f

typedef unsigned long long ull;

// ---------------- device scratch ----------------------------------------------
__device__ __half g_zh[N_NODES * D];       // z = h@W, fp16
__device__ float  g_wa[256];               // [W@a1 ; W@a2] (row-dots of W)
__device__ float  g_ssrc[N_NODES];
__device__ float  g_sdst[N_NODES];
__device__ int    g_cnt[N_NODES];          // in-degree histogram (self-cleaning)
__device__ int    g_rank[N_EDGES];         // rank of edge within its dst segment
__device__ int    g_loc[N_NODES];          // block-local exclusive scan
__device__ int    g_part[128];             // per-block totals
__device__ int    g_rowptr[N_NODES + 1];
__device__ int2   g_edge[N_EDGES];         // (src, exp(leaky(score)) bits), by dst

// ---------------- f32x2 helpers ------------------------------------------------
__device__ __forceinline__ ull ffma2(ull a, ull b, ull c) {
    ull d;
    asm("fma.rn.f32x2 %0, %1, %2, %3;" : "=l"(d) : "l"(a), "l"(b), "l"(c));
    return d;
}
__device__ __forceinline__ ull fadd2(ull a, ull b) {
    ull d;
    asm("add.rn.f32x2 %0, %1, %2;" : "=l"(d) : "l"(a), "l"(b));
    return d;
}
__device__ __forceinline__ ull pack2(float x, float y) {
    ull d;
    asm("mov.b64 %0, {%1, %2};" : "=l"(d) : "f"(x), "f"(y));
    return d;
}
__device__ __forceinline__ float2 unpack2(ull v) {
    float2 r;
    asm("mov.b64 {%0, %1}, %2;" : "=f"(r.x), "=f"(r.y) : "l"(v));
    return r;
}

// ---------------- 0) score factorization: wa[k] = W[k,:]@a --------------------
// s_src = (hW)@a1 = h@(W@a1). Thread t<128 owns row t of W against a1;
// thread t>=128 owns row t-128 against a2. FIXED: contract over COLUMNS of W.
__global__ void wproj_kernel(const float* __restrict__ W,
                             const float* __restrict__ attn) {
    int t = threadIdx.x;                       // 256
    int k = t & 127;                           // W row
    const float* a = attn + ((t >> 7) << 7);   // a1 for t<128, a2 for t>=128
    const float* wr = W + k * D;               // row k, contiguous
    float s = 0.f;
#pragma unroll 8
    for (int c = 0; c < 128; c++)
        s = fmaf(wr[c], a[c], s);
    g_wa[t] = s;
}

// per-node dots from h (warp per row, coalesced)
__global__ void sdots_kernel(const float* __restrict__ h) {
    int gw   = (blockIdx.x * blockDim.x + threadIdx.x) >> 5;
    int lane = threadIdx.x & 31;
    if (gw >= N_NODES) return;
    float4 v  = *(const float4*)(h + (size_t)gw * D + lane * 4);
    float4 w1 = *(const float4*)(g_wa + lane * 4);
    float4 w2 = *(const float4*)(g_wa + 128 + lane * 4);
    float p = v.x * w1.x + v.y * w1.y + v.z * w1.z + v.w * w1.w;
    float q = v.x * w2.x + v.y * w2.y + v.z * w2.z + v.w * w2.w;
#pragma unroll
    for (int off = 16; off; off >>= 1) {
        p += __shfl_xor_sync(0xffffffffu, p, off);
        q += __shfl_xor_sync(0xffffffffu, q, off);
    }
    if (lane == 0) { g_ssrc[gw] = p; g_sdst[gw] = q; }
}

// ---------------- 1) GEMM z = h@W via HMMA (M=64 tile, 256 thr, 4 blk/SM) -----
// Warp grid 2(m)x4(n), warp tile 32x32 = 2x2 wmma frags. smem 52 KB -> 4/SM.
#define APITCH 136   // half pitch for A/B smem tiles
#define CPITCH 132   // float pitch for C smem tile
#define GEMM_SMEM ((64 + 128) * APITCH * 2)   // 52224 B (Cs 64*132*4=33792 overlays)

__global__ void gemm_kernel(const float* __restrict__ h, const float* __restrict__ W) {
    extern __shared__ char smem[];
    __half* As = (__half*)smem;                      // [64][APITCH]  (h tile, [m][k])
    __half* Bs = (__half*)(smem + 64 * APITCH * 2);  // [128][APITCH] (W, [k][n])
    float*  Cs = (float*)smem;                       // [64][CPITCH] overlay

    const int tid  = threadIdx.x;                    // 256 threads
    const int row0 = blockIdx.x * 64;

    // stage W -> fp16 smem (16 iters/thread; L2-resident after first wave)
    for (int i = tid; i < 128 * 32; i += 256) {
        int k = i >> 5, c4 = i & 31;
        float4 v = *(const float4*)(W + k * D + c4 * 4);
        __half2 h0 = __floats2half2_rn(v.x, v.y);
        __half2 h1 = __floats2half2_rn(v.z, v.w);
        uint2 u;
        u.x = *(unsigned*)&h0;
        u.y = *(unsigned*)&h1;
        *(uint2*)(Bs + k * APITCH + c4 * 4) = u;
    }
    // stage h tile -> fp16 smem (8 iters/thread)
    for (int i = tid; i < 64 * 32; i += 256) {
        int r = i >> 5, c4 = i & 31;
        int row = row0 + r;
        float4 v = make_float4(0.f, 0.f, 0.f, 0.f);
        if (row < N_NODES) v = *(const float4*)(h + (size_t)row * D + c4 * 4);
        __half2 h0 = __floats2half2_rn(v.x, v.y);
        __half2 h1 = __floats2half2_rn(v.z, v.w);
        uint2 u;
        u.x = *(unsigned*)&h0;
        u.y = *(unsigned*)&h1;
        *(uint2*)(As + r * APITCH + c4 * 4) = u;
    }
    __syncthreads();

    const int warp = tid >> 5;      // 0..7
    const int wm = warp & 1;        // rows wm*32
    const int wn = warp >> 1;       // cols wn*32

    wmma::fragment<wmma::accumulator, 16, 16, 16, float> acc[2][2];
#pragma unroll
    for (int i = 0; i < 2; i++)
#pragma unroll
        for (int j = 0; j < 2; j++) wmma::fill_fragment(acc[i][j], 0.f);

#pragma unroll
    for (int k0 = 0; k0 < 8; k0++) {
        wmma::fragment<wmma::matrix_a, 16, 16, 16, __half, wmma::row_major> af[2];
        wmma::fragment<wmma::matrix_b, 16, 16, 16, __half, wmma::row_major> bf[2];
#pragma unroll
        for (int i = 0; i < 2; i++)
            wmma::load_matrix_sync(af[i], As + (wm * 32 + i * 16) * APITCH + k0 * 16, APITCH);
#pragma unroll
        for (int j = 0; j < 2; j++)
            wmma::load_matrix_sync(bf[j], Bs + (k0 * 16) * APITCH + wn * 32 + j * 16, APITCH);
#pragma unroll
        for (int i = 0; i < 2; i++)
#pragma unroll
            for (int j = 0; j < 2; j++)
                wmma::mma_sync(acc[i][j], af[i], bf[j], acc[i][j]);
    }

    __syncthreads();   // done reading As/Bs; reuse smem as Cs
#pragma unroll
    for (int i = 0; i < 2; i++)
#pragma unroll
        for (int j = 0; j < 2; j++)
            wmma::store_matrix_sync(Cs + (wm * 32 + i * 16) * CPITCH + wn * 32 + j * 16,
                                    acc[i][j], CPITCH, wmma::mem_row_major);
    __syncthreads();

    // epilogue: 4 threads/row, 32 cols each; fp16 z store only
    {
        int r    = tid >> 2;          // 0..63
        int part = tid & 3;
        int c0   = part * 32;
        int row  = row0 + r;
        if (row < N_NODES) {
            const float* crow = Cs + r * CPITCH + c0;
            __half* zrow = g_zh + (size_t)row * D + c0;
#pragma unroll
            for (int c = 0; c < 32; c += 4) {
                float4 v = *(const float4*)(crow + c);
                __half2 h0 = __floats2half2_rn(v.x, v.y);
                __half2 h1 = __floats2half2_rn(v.z, v.w);
                uint2 u;
                u.x = *(unsigned*)&h0;
                u.y = *(unsigned*)&h1;
                *(uint2*)(zrow + c) = u;
            }
        }
    }
}

// ---------------- 2) CSR build (edge-index-only) ------------------------------
__global__ void hist_kernel(const int* __restrict__ edst) {
    int i = blockIdx.x * blockDim.x + threadIdx.x;
    if (i < N_EDGES) g_rank[i] = atomicAdd(&g_cnt[edst[i]], 1);
}

__global__ void scanA_kernel() {   // 98 blocks x 1024, shfl-based
    __shared__ int wsum[32];
    int t = threadIdx.x, lane = t & 31, w = t >> 5;
    int i = blockIdx.x * 1024 + t;
    int v = (i < N_NODES) ? g_cnt[i] : 0;
    int x = v;
#pragma unroll
    for (int off = 1; off < 32; off <<= 1) {
        int y = __shfl_up_sync(0xffffffffu, x, off);
        if (lane >= off) x += y;
    }
    if (lane == 31) wsum[w] = x;
    __syncthreads();
    if (t < 32) {
        int tot = wsum[t];
        int xs = tot;
#pragma unroll
        for (int off = 1; off < 32; off <<= 1) {
            int y = __shfl_up_sync(0xffffffffu, xs, off);
            if (t >= off) xs += y;
        }
        wsum[t] = xs - tot;
        if (t == 31) g_part[blockIdx.x] = xs;
    }
    __syncthreads();
    if (i < N_NODES) g_loc[i] = x + wsum[w] - v;
}

// merged scanB+scanC: each block redundantly scans the 98 partials, emits rowptr,
// and re-zeroes g_cnt (self-cleaning for graph replay).
__global__ void scanC_kernel() {
    __shared__ int s[128];
    const int NB = (N_NODES + 1023) / 1024;
    int t = threadIdx.x;            // 256 threads
    if (t < 128) {
        int v = (t < NB) ? g_part[t] : 0;
        s[t] = v;
    }
    __syncthreads();
#pragma unroll
    for (int off = 1; off < 128; off <<= 1) {
        int tmp = 0;
        if (t < 128 && t >= off) tmp = s[t - off];
        __syncthreads();
        if (t < 128) s[t] += tmp;
        __syncthreads();
    }
    int i = blockIdx.x * blockDim.x + t;
    if (i < N_NODES) {
        int b = i >> 10;
        int poff = s[b] - ((b < NB) ? g_part[b] : 0);
        g_rowptr[i] = g_loc[i] + poff;
        g_cnt[i] = 0;
    }
    if (i == 0) g_rowptr[N_NODES] = N_EDGES;
}

// ---------------- 3) fused scatter + weight (needs scores + rowptr, NOT GEMM) -
// Softmax without max-shift is exact here (|score| < ~8, exp cannot overflow).
__global__ void scatterw_kernel(const int* __restrict__ esrc,
                                const int* __restrict__ edst) {
    int i = blockIdx.x * blockDim.x + threadIdx.x;
    if (i < N_EDGES) {
        int d = edst[i];
        int s = esrc[i];
        int pos = g_rowptr[d] + g_rank[i];
        float sc = g_ssrc[s] + g_sdst[d];
        sc = (sc > 0.f) ? sc : NEG_SLOPE * sc;
        g_edge[pos] = make_int2(s, __float_as_int(__expf(sc)));
    }
}

// ---------------- 4) aggregate: warp/node, edge-PAIRS via half-warp rows ------
__device__ __forceinline__ void acc_pair(int jj, float wgt, int s, int qoff,
                                         ull& a0, ull& a1, ull& a2, ull& a3) {
    float wj = __shfl_sync(0xffffffffu, wgt, jj);
    int   sj = __shfl_sync(0xffffffffu, s, jj);
    uint4 u = *(const uint4*)(g_zh + (size_t)sj * D + qoff);
    ull wd = pack2(wj, wj);
    float2 f;
    f = __half22float2(*(__half2*)&u.x); a0 = ffma2(pack2(f.x, f.y), wd, a0);
    f = __half22float2(*(__half2*)&u.y); a1 = ffma2(pack2(f.x, f.y), wd, a1);
    f = __half22float2(*(__half2*)&u.z); a2 = ffma2(pack2(f.x, f.y), wd, a2);
    f = __half22float2(*(__half2*)&u.w); a3 = ffma2(pack2(f.x, f.y), wd, a3);
}

__global__ void aggregate_kernel(float* __restrict__ out) {
    int gw   = (blockIdx.x * blockDim.x + threadIdx.x) >> 5;
    int lane = threadIdx.x & 31;
    if (gw >= N_NODES) return;

    int q  = lane & 15;           // column group: cols 8q..8q+7
    int hi = lane >> 4;           // even/odd edge of pair
    int qoff = q * 8;

    int beg = g_rowptr[gw];
    int end = g_rowptr[gw + 1];
    float* owr = out + (size_t)gw * D + qoff + hi * 4;

    if (beg == end) {
        *(float4*)owr = make_float4(0.f, 0.f, 0.f, 0.f);
        return;
    }

    ull a0 = 0ull, a1 = 0ull, a2 = 0ull, a3 = 0ull;
    float denom = 0.f;

    for (int base = beg; base < end; base += 32) {
        int   i = base + lane;
        int   s = 0;
        float wgt = 0.f;
        if (i < end) {
            int2 e = g_edge[i];           // coalesced LDG.64: (src, w)
            s = e.x;
            wgt = __int_as_float(e.y);
        }
        denom += wgt;
        int cnt = end - base;
        if (cnt > 32) cnt = 32;

        int j = 0;
        for (; j + 8 <= cnt; j += 8) {
            int   jj0 = j + 0 + hi, jj1 = j + 2 + hi, jj2 = j + 4 + hi, jj3 = j + 6 + hi;
            float w0 = __shfl_sync(0xffffffffu, wgt, jj0);
            float w1 = __shfl_sync(0xffffffffu, wgt, jj1);
            float w2 = __shfl_sync(0xffffffffu, wgt, jj2);
            float w3 = __shfl_sync(0xffffffffu, wgt, jj3);
            int   s0 = __shfl_sync(0xffffffffu, s, jj0);
            int   s1 = __shfl_sync(0xffffffffu, s, jj1);
            int   s2 = __shfl_sync(0xffffffffu, s, jj2);
            int   s3 = __shfl_sync(0xffffffffu, s, jj3);
            uint4 u0 = *(const uint4*)(g_zh + (size_t)s0 * D + qoff);
            uint4 u1 = *(const uint4*)(g_zh + (size_t)s1 * D + qoff);
            uint4 u2 = *(const uint4*)(g_zh + (size_t)s2 * D + qoff);
            uint4 u3 = *(const uint4*)(g_zh + (size_t)s3 * D + qoff);
            ull wd; float2 f;
            wd = pack2(w0, w0);
            f = __half22float2(*(__half2*)&u0.x); a0 = ffma2(pack2(f.x, f.y), wd, a0);
            f = __half22float2(*(__half2*)&u0.y); a1 = ffma2(pack2(f.x, f.y), wd, a1);
            f = __half22float2(*(__half2*)&u0.z); a2 = ffma2(pack2(f.x, f.y), wd, a2);
            f = __half22float2(*(__half2*)&u0.w); a3 = ffma2(pack2(f.x, f.y), wd, a3);
            wd = pack2(w1, w1);
            f = __half22float2(*(__half2*)&u1.x); a0 = ffma2(pack2(f.x, f.y), wd, a0);
            f = __half22float2(*(__half2*)&u1.y); a1 = ffma2(pack2(f.x, f.y), wd, a1);
            f = __half22float2(*(__half2*)&u1.z); a2 = ffma2(pack2(f.x, f.y), wd, a2);
            f = __half22float2(*(__half2*)&u1.w); a3 = ffma2(pack2(f.x, f.y), wd, a3);
            wd = pack2(w2, w2);
            f = __half22float2(*(__half2*)&u2.x); a0 = ffma2(pack2(f.x, f.y), wd, a0);
            f = __half22float2(*(__half2*)&u2.y); a1 = ffma2(pack2(f.x, f.y), wd, a1);
            f = __half22float2(*(__half2*)&u2.z); a2 = ffma2(pack2(f.x, f.y), wd, a2);
            f = __half22float2(*(__half2*)&u2.w); a3 = ffma2(pack2(f.x, f.y), wd, a3);
            wd = pack2(w3, w3);
            f = __half22float2(*(__half2*)&u3.x); a0 = ffma2(pack2(f.x, f.y), wd, a0);
            f = __half22float2(*(__half2*)&u3.y); a1 = ffma2(pack2(f.x, f.y), wd, a1);
            f = __half22float2(*(__half2*)&u3.z); a2 = ffma2(pack2(f.x, f.y), wd, a2);
            f = __half22float2(*(__half2*)&u3.w); a3 = ffma2(pack2(f.x, f.y), wd, a3);
        }
        for (; j < cnt; j += 2)
            acc_pair(j + hi, wgt, s, qoff, a0, a1, a2, a3);
    }

    a0 = fadd2(a0, __shfl_xor_sync(0xffffffffu, a0, 16));
    a1 = fadd2(a1, __shfl_xor_sync(0xffffffffu, a1, 16));
    a2 = fadd2(a2, __shfl_xor_sync(0xffffffffu, a2, 16));
    a3 = fadd2(a3, __shfl_xor_sync(0xffffffffu, a3, 16));
#pragma unroll
    for (int off = 16; off; off >>= 1)
        denom += __shfl_xor_sync(0xffffffffu, denom, off);

    float inv = 1.f / denom;
    float2 r0 = unpack2(a0), r1 = unpack2(a1), r2 = unpack2(a2), r3 = unpack2(a3);
    float4 res = hi ? make_float4(r2.x * inv, r2.y * inv, r3.x * inv, r3.y * inv)
                    : make_float4(r0.x * inv, r0.y * inv, r1.x * inv, r1.y * inv);
    *(float4*)owr = res;
}

// ---------------- launch: 3-way fork (GEMM || CSR || scores), tail = aggregate
extern "C" void kernel_launch(void* const* d_in, const int* in_sizes, int n_in,
                              void* d_out, int out_size) {
    const float* h    = (const float*)d_in[0];
    const float* W    = (const float*)d_in[1];
    const float* attn = (const float*)d_in[2];
    const int*   esrc = (const int*)d_in[3];
    const int*   edst = (const int*)d_in[4];
    float*       out  = (float*)d_out;

    static cudaStream_t s1 = nullptr, s2 = nullptr;
    static cudaEvent_t  evFork = nullptr, evS2 = nullptr, evJoin = nullptr;
    if (s1 == nullptr) {   // first call is the uncaptured correctness run
        cudaStreamCreateWithFlags(&s1, cudaStreamNonBlocking);
        cudaStreamCreateWithFlags(&s2, cudaStreamNonBlocking);
        cudaEventCreateWithFlags(&evFork, cudaEventDisableTiming);
        cudaEventCreateWithFlags(&evS2, cudaEventDisableTiming);
        cudaEventCreateWithFlags(&evJoin, cudaEventDisableTiming);
        cudaFuncSetAttribute(gemm_kernel,
                             cudaFuncAttributeMaxDynamicSharedMemorySize, GEMM_SMEM);
    }

    // fork from main to s1 (CSR) and s2 (scores)
    cudaEventRecord(evFork, 0);
    cudaStreamWaitEvent(s1, evFork, 0);
    cudaStreamWaitEvent(s2, evFork, 0);

    // launch order chosen so gemm is the 4th kernel (profiler window)
    wproj_kernel<<<1, 256, 0, s2>>>(W, attn);                              // 1
    sdots_kernel<<<(N_NODES * 32 + 255) / 256, 256, 0, s2>>>(h);           // 2
    hist_kernel<<<(N_EDGES + 255) / 256, 256, 0, s1>>>(edst);              // 3
    const int gemm_blocks = (N_NODES + 63) / 64;                           // 1563
    gemm_kernel<<<gemm_blocks, 256, GEMM_SMEM>>>(h, W);                    // 4 (main)
    scanA_kernel<<<(N_NODES + 1023) / 1024, 1024, 0, s1>>>();              // 5
    scanC_kernel<<<(N_NODES + 255) / 256, 256, 0, s1>>>();                 // 6

    // scatterw on s1 needs scores from s2
    cudaEventRecord(evS2, s2);
    cudaStreamWaitEvent(s1, evS2, 0);
    scatterw_kernel<<<(N_EDGES + 255) / 256, 256, 0, s1>>>(esrc, edst);    // 7

    // join: aggregate needs gemm (main) + scatterw (s1)
    cudaEventRecord(evJoin, s1);
    cudaStreamWaitEvent(0, evJoin, 0);
    aggregate_kernel<<<(N_NODES * 32 + 255) / 256, 256>>>(out);            // 8
}

// round 15
// speedup vs baseline: 1.0525x; 1.0525x over previous
#include <cuda_runtime.h>
#include <cuda_fp16.h>
#include <mma.h>

using namespace nvcuda;

#define N_NODES 100000
#define N_EDGES 1600000
#define D 128
#define NEG_SLOPE 0.01f

typedef unsigned long long ull;

// ---------------- device scratch ----------------------------------------------
__device__ __half g_zh[N_NODES * D];       // z = h@W, fp16
__device__ float  g_ssrc[N_NODES];
__device__ float  g_sdst[N_NODES];
__device__ int    g_cnt[N_NODES];          // in-degree histogram (self-cleaning)
__device__ int    g_rank[N_EDGES];         // rank of edge within its dst segment
__device__ int    g_loc[N_NODES];          // block-local exclusive scan
__device__ int    g_part[128];             // per-block totals
__device__ int    g_rowptr[N_NODES + 1];
__device__ int    g_srcs[N_EDGES];         // src ids grouped by dst (score-free!)

// ---------------- f32x2 helpers ------------------------------------------------
__device__ __forceinline__ ull ffma2(ull a, ull b, ull c) {
    ull d;
    asm("fma.rn.f32x2 %0, %1, %2, %3;" : "=l"(d) : "l"(a), "l"(b), "l"(c));
    return d;
}
__device__ __forceinline__ ull fadd2(ull a, ull b) {
    ull d;
    asm("add.rn.f32x2 %0, %1, %2;" : "=l"(d) : "l"(a), "l"(b));
    return d;
}
__device__ __forceinline__ ull pack2(float x, float y) {
    ull d;
    asm("mov.b64 %0, {%1, %2};" : "=l"(d) : "f"(x), "f"(y));
    return d;
}
__device__ __forceinline__ float2 unpack2(ull v) {
    float2 r;
    asm("mov.b64 {%0, %1}, %2;" : "=f"(r.x), "=f"(r.y) : "l"(v));
    return r;
}

// ---------------- 1) GEMM z = h@W via HMMA (M=64 tile) + fused fp32 dots ------
// Warp grid 2(m)x4(n), warp tile 32x32 = 2x2 wmma frags. smem 52 KB -> 4 blk/SM.
// Epilogue computes s_src/s_dst from the fp32 C tile (no extra DRAM pass).
#define APITCH 136   // half pitch for A/B smem tiles
#define CPITCH 132   // float pitch for C smem tile
#define GEMM_SMEM ((64 + 128) * APITCH * 2)   // 52224 B (Cs 64*132*4=33792 overlays)

__global__ void gemm_kernel(const float* __restrict__ h, const float* __restrict__ W,
                            const float* __restrict__ attn) {
    extern __shared__ char smem[];
    __half* As = (__half*)smem;                      // [64][APITCH]  (h tile, [m][k])
    __half* Bs = (__half*)(smem + 64 * APITCH * 2);  // [128][APITCH] (W, [k][n])
    float*  Cs = (float*)smem;                       // [64][CPITCH] overlay

    const int tid  = threadIdx.x;                    // 256 threads
    const int row0 = blockIdx.x * 64;

    // stage W -> fp16 smem (L2-resident after first wave)
    for (int i = tid; i < 128 * 32; i += 256) {
        int k = i >> 5, c4 = i & 31;
        float4 v = *(const float4*)(W + k * D + c4 * 4);
        __half2 h0 = __floats2half2_rn(v.x, v.y);
        __half2 h1 = __floats2half2_rn(v.z, v.w);
        uint2 u;
        u.x = *(unsigned*)&h0;
        u.y = *(unsigned*)&h1;
        *(uint2*)(Bs + k * APITCH + c4 * 4) = u;
    }
    // stage h tile -> fp16 smem
    for (int i = tid; i < 64 * 32; i += 256) {
        int r = i >> 5, c4 = i & 31;
        int row = row0 + r;
        float4 v = make_float4(0.f, 0.f, 0.f, 0.f);
        if (row < N_NODES) v = *(const float4*)(h + (size_t)row * D + c4 * 4);
        __half2 h0 = __floats2half2_rn(v.x, v.y);
        __half2 h1 = __floats2half2_rn(v.z, v.w);
        uint2 u;
        u.x = *(unsigned*)&h0;
        u.y = *(unsigned*)&h1;
        *(uint2*)(As + r * APITCH + c4 * 4) = u;
    }
    __syncthreads();

    const int warp = tid >> 5;      // 0..7
    const int wm = warp & 1;        // rows wm*32
    const int wn = warp >> 1;       // cols wn*32

    wmma::fragment<wmma::accumulator, 16, 16, 16, float> acc[2][2];
#pragma unroll
    for (int i = 0; i < 2; i++)
#pragma unroll
        for (int j = 0; j < 2; j++) wmma::fill_fragment(acc[i][j], 0.f);

#pragma unroll
    for (int k0 = 0; k0 < 8; k0++) {
        wmma::fragment<wmma::matrix_a, 16, 16, 16, __half, wmma::row_major> af[2];
        wmma::fragment<wmma::matrix_b, 16, 16, 16, __half, wmma::row_major> bf[2];
#pragma unroll
        for (int i = 0; i < 2; i++)
            wmma::load_matrix_sync(af[i], As + (wm * 32 + i * 16) * APITCH + k0 * 16, APITCH);
#pragma unroll
        for (int j = 0; j < 2; j++)
            wmma::load_matrix_sync(bf[j], Bs + (k0 * 16) * APITCH + wn * 32 + j * 16, APITCH);
#pragma unroll
        for (int i = 0; i < 2; i++)
#pragma unroll
            for (int j = 0; j < 2; j++)
                wmma::mma_sync(acc[i][j], af[i], bf[j], acc[i][j]);
    }

    __syncthreads();   // done reading As/Bs; reuse smem as Cs
#pragma unroll
    for (int i = 0; i < 2; i++)
#pragma unroll
        for (int j = 0; j < 2; j++)
            wmma::store_matrix_sync(Cs + (wm * 32 + i * 16) * CPITCH + wn * 32 + j * 16,
                                    acc[i][j], CPITCH, wmma::mem_row_major);
    __syncthreads();

    // epilogue: 4 threads/row, 32 cols each; fused fp32 dots + fp16 z store
    {
        int r    = tid >> 2;          // 0..63
        int part = tid & 3;           // adjacent lanes within a warp
        int c0   = part * 32;
        int row  = row0 + r;
        float p = 0.f, q = 0.f;
        if (row < N_NODES) {
            const float* crow = Cs + r * CPITCH + c0;
            __half* zrow = g_zh + (size_t)row * D + c0;
#pragma unroll
            for (int c = 0; c < 32; c += 4) {
                float4 v  = *(const float4*)(crow + c);
                float4 a1 = *(const float4*)(attn + c0 + c);
                float4 a2 = *(const float4*)(attn + D + c0 + c);
                p += v.x * a1.x + v.y * a1.y + v.z * a1.z + v.w * a1.w;
                q += v.x * a2.x + v.y * a2.y + v.z * a2.z + v.w * a2.w;
                __half2 h0 = __floats2half2_rn(v.x, v.y);
                __half2 h1 = __floats2half2_rn(v.z, v.w);
                uint2 u;
                u.x = *(unsigned*)&h0;
                u.y = *(unsigned*)&h1;
                *(uint2*)(zrow + c) = u;
            }
        }
        // combine 4 partials (lanes 4r..4r+3 adjacent within a warp)
        p += __shfl_xor_sync(0xffffffffu, p, 1);
        q += __shfl_xor_sync(0xffffffffu, q, 1);
        p += __shfl_xor_sync(0xffffffffu, p, 2);
        q += __shfl_xor_sync(0xffffffffu, q, 2);
        if (part == 0 && row < N_NODES) {
            g_ssrc[row] = p;
            g_sdst[row] = q;
        }
    }
}

// ---------------- 2) CSR build + score-free scatter (runs fully || GEMM) ------
__global__ void hist_kernel(const int* __restrict__ edst) {
    int i = blockIdx.x * blockDim.x + threadIdx.x;
    if (i < N_EDGES) g_rank[i] = atomicAdd(&g_cnt[edst[i]], 1);
}

__global__ void scanA_kernel() {   // 98 blocks x 1024, shfl-based
    __shared__ int wsum[32];
    int t = threadIdx.x, lane = t & 31, w = t >> 5;
    int i = blockIdx.x * 1024 + t;
    int v = (i < N_NODES) ? g_cnt[i] : 0;
    int x = v;
#pragma unroll
    for (int off = 1; off < 32; off <<= 1) {
        int y = __shfl_up_sync(0xffffffffu, x, off);
        if (lane >= off) x += y;
    }
    if (lane == 31) wsum[w] = x;
    __syncthreads();
    if (t < 32) {
        int tot = wsum[t];
        int xs = tot;
#pragma unroll
        for (int off = 1; off < 32; off <<= 1) {
            int y = __shfl_up_sync(0xffffffffu, xs, off);
            if (t >= off) xs += y;
        }
        wsum[t] = xs - tot;
        if (t == 31) g_part[blockIdx.x] = xs;
    }
    __syncthreads();
    if (i < N_NODES) g_loc[i] = x + wsum[w] - v;
}

// merged scanB+scanC: each block redundantly scans the 98 partials, emits rowptr,
// and re-zeroes g_cnt (self-cleaning for graph replay).
__global__ void scanC_kernel() {
    __shared__ int s[128];
    const int NB = (N_NODES + 1023) / 1024;
    int t = threadIdx.x;            // 256 threads
    if (t < 128) {
        int v = (t < NB) ? g_part[t] : 0;
        s[t] = v;
    }
    __syncthreads();
#pragma unroll
    for (int off = 1; off < 128; off <<= 1) {
        int tmp = 0;
        if (t < 128 && t >= off) tmp = s[t - off];
        __syncthreads();
        if (t < 128) s[t] += tmp;
        __syncthreads();
    }
    int i = blockIdx.x * blockDim.x + t;
    if (i < N_NODES) {
        int b = i >> 10;
        int poff = s[b] - ((b < NB) ? g_part[b] : 0);
        g_rowptr[i] = g_loc[i] + poff;
        g_cnt[i] = 0;
    }
    if (i == 0) g_rowptr[N_NODES] = N_EDGES;
}

// scatter src ids only — no GEMM/score dependency, lives in the parallel branch
__global__ void scatter_src_kernel(const int* __restrict__ esrc,
                                   const int* __restrict__ edst) {
    int i = blockIdx.x * blockDim.x + threadIdx.x;
    if (i < N_EDGES) {
        int d = edst[i];
        g_srcs[g_rowptr[d] + g_rank[i]] = esrc[i];
    }
}

// ---------------- 3) aggregate: warp/node, inline exp, pair-gather ------------
// Softmax without max-shift is exact here (|score| < ~8, exp cannot overflow).
// lanes 0-15 carry edge j's z-row half (16B/lane), lanes 16-31 edge j+1's.
__device__ __forceinline__ void acc_pair(int jj, float wgt, int s, int qoff,
                                         ull& a0, ull& a1, ull& a2, ull& a3) {
    float wj = __shfl_sync(0xffffffffu, wgt, jj);
    int   sj = __shfl_sync(0xffffffffu, s, jj);
    uint4 u = *(const uint4*)(g_zh + (size_t)sj * D + qoff);
    ull wd = pack2(wj, wj);
    float2 f;
    f = __half22float2(*(__half2*)&u.x); a0 = ffma2(pack2(f.x, f.y), wd, a0);
    f = __half22float2(*(__half2*)&u.y); a1 = ffma2(pack2(f.x, f.y), wd, a1);
    f = __half22float2(*(__half2*)&u.z); a2 = ffma2(pack2(f.x, f.y), wd, a2);
    f = __half22float2(*(__half2*)&u.w); a3 = ffma2(pack2(f.x, f.y), wd, a3);
}

__global__ void aggregate_kernel(float* __restrict__ out) {
    int gw   = (blockIdx.x * blockDim.x + threadIdx.x) >> 5;
    int lane = threadIdx.x & 31;
    if (gw >= N_NODES) return;

    int q  = lane & 15;           // column group: cols 8q..8q+7
    int hi = lane >> 4;           // even/odd edge of pair
    int qoff = q * 8;

    int beg = g_rowptr[gw];
    int end = g_rowptr[gw + 1];
    float* owr = out + (size_t)gw * D + qoff + hi * 4;

    if (beg == end) {
        *(float4*)owr = make_float4(0.f, 0.f, 0.f, 0.f);
        return;
    }

    float sd = g_sdst[gw];
    ull a0 = 0ull, a1 = 0ull, a2 = 0ull, a3 = 0ull;
    float denom = 0.f;

    for (int base = beg; base < end; base += 32) {
        int   i = base + lane;
        int   s = 0;
        float wgt = 0.f;
        if (i < end) {
            s = g_srcs[i];                // coalesced LDG.32
            float e = g_ssrc[s] + sd;     // random 4B gather, L2-resident
            e = (e > 0.f) ? e : NEG_SLOPE * e;
            wgt = __expf(e);
        }
        denom += wgt;
        int cnt = end - base;
        if (cnt > 32) cnt = 32;

        int j = 0;
        for (; j + 8 <= cnt; j += 8) {
            int   jj0 = j + 0 + hi, jj1 = j + 2 + hi, jj2 = j + 4 + hi, jj3 = j + 6 + hi;
            float w0 = __shfl_sync(0xffffffffu, wgt, jj0);
            float w1 = __shfl_sync(0xffffffffu, wgt, jj1);
            float w2 = __shfl_sync(0xffffffffu, wgt, jj2);
            float w3 = __shfl_sync(0xffffffffu, wgt, jj3);
            int   s0 = __shfl_sync(0xffffffffu, s, jj0);
            int   s1 = __shfl_sync(0xffffffffu, s, jj1);
            int   s2 = __shfl_sync(0xffffffffu, s, jj2);
            int   s3 = __shfl_sync(0xffffffffu, s, jj3);
            uint4 u0 = *(const uint4*)(g_zh + (size_t)s0 * D + qoff);
            uint4 u1 = *(const uint4*)(g_zh + (size_t)s1 * D + qoff);
            uint4 u2 = *(const uint4*)(g_zh + (size_t)s2 * D + qoff);
            uint4 u3 = *(const uint4*)(g_zh + (size_t)s3 * D + qoff);
            ull wd; float2 f;
            wd = pack2(w0, w0);
            f = __half22float2(*(__half2*)&u0.x); a0 = ffma2(pack2(f.x, f.y), wd, a0);
            f = __half22float2(*(__half2*)&u0.y); a1 = ffma2(pack2(f.x, f.y), wd, a1);
            f = __half22float2(*(__half2*)&u0.z); a2 = ffma2(pack2(f.x, f.y), wd, a2);
            f = __half22float2(*(__half2*)&u0.w); a3 = ffma2(pack2(f.x, f.y), wd, a3);
            wd = pack2(w1, w1);
            f = __half22float2(*(__half2*)&u1.x); a0 = ffma2(pack2(f.x, f.y), wd, a0);
            f = __half22float2(*(__half2*)&u1.y); a1 = ffma2(pack2(f.x, f.y), wd, a1);
            f = __half22float2(*(__half2*)&u1.z); a2 = ffma2(pack2(f.x, f.y), wd, a2);
            f = __half22float2(*(__half2*)&u1.w); a3 = ffma2(pack2(f.x, f.y), wd, a3);
            wd = pack2(w2, w2);
            f = __half22float2(*(__half2*)&u2.x); a0 = ffma2(pack2(f.x, f.y), wd, a0);
            f = __half22float2(*(__half2*)&u2.y); a1 = ffma2(pack2(f.x, f.y), wd, a1);
            f = __half22float2(*(__half2*)&u2.z); a2 = ffma2(pack2(f.x, f.y), wd, a2);
            f = __half22float2(*(__half2*)&u2.w); a3 = ffma2(pack2(f.x, f.y), wd, a3);
            wd = pack2(w3, w3);
            f = __half22float2(*(__half2*)&u3.x); a0 = ffma2(pack2(f.x, f.y), wd, a0);
            f = __half22float2(*(__half2*)&u3.y); a1 = ffma2(pack2(f.x, f.y), wd, a1);
            f = __half22float2(*(__half2*)&u3.z); a2 = ffma2(pack2(f.x, f.y), wd, a2);
            f = __half22float2(*(__half2*)&u3.w); a3 = ffma2(pack2(f.x, f.y), wd, a3);
        }
        for (; j < cnt; j += 2)
            acc_pair(j + hi, wgt, s, qoff, a0, a1, a2, a3);
    }

    a0 = fadd2(a0, __shfl_xor_sync(0xffffffffu, a0, 16));
    a1 = fadd2(a1, __shfl_xor_sync(0xffffffffu, a1, 16));
    a2 = fadd2(a2, __shfl_xor_sync(0xffffffffu, a2, 16));
    a3 = fadd2(a3, __shfl_xor_sync(0xffffffffu, a3, 16));
#pragma unroll
    for (int off = 16; off; off >>= 1)
        denom += __shfl_xor_sync(0xffffffffu, denom, off);

    float inv = 1.f / denom;
    float2 r0 = unpack2(a0), r1 = unpack2(a1), r2 = unpack2(a2), r3 = unpack2(a3);
    float4 res = hi ? make_float4(r2.x * inv, r2.y * inv, r3.x * inv, r3.y * inv)
                    : make_float4(r0.x * inv, r0.y * inv, r1.x * inv, r1.y * inv);
    *(float4*)owr = res;
}

// ---------------- launch: 2-stream fork-join, tail = aggregate only -----------
extern "C" void kernel_launch(void* const* d_in, const int* in_sizes, int n_in,
                              void* d_out, int out_size) {
    const float* h    = (const float*)d_in[0];
    const float* W    = (const float*)d_in[1];
    const float* attn = (const float*)d_in[2];
    const int*   esrc = (const int*)d_in[3];
    const int*   edst = (const int*)d_in[4];
    float*       out  = (float*)d_out;

    static cudaStream_t s1 = nullptr;
    static cudaEvent_t  evFork = nullptr, evJoin = nullptr;
    if (s1 == nullptr) {   // first call is the uncaptured correctness run
        cudaStreamCreateWithFlags(&s1, cudaStreamNonBlocking);
        cudaEventCreateWithFlags(&evFork, cudaEventDisableTiming);
        cudaEventCreateWithFlags(&evJoin, cudaEventDisableTiming);
        cudaFuncSetAttribute(gemm_kernel,
                             cudaFuncAttributeMaxDynamicSharedMemorySize, GEMM_SMEM);
    }

    // fork
    cudaEventRecord(evFork, 0);
    cudaStreamWaitEvent(s1, evFork, 0);

    // CSR branch (s1): hist(1) scanA(2) scanC(3) scatter_src(5)
    hist_kernel<<<(N_EDGES + 255) / 256, 256, 0, s1>>>(edst);              // 1
    scanA_kernel<<<(N_NODES + 1023) / 1024, 1024, 0, s1>>>();              // 2
    scanC_kernel<<<(N_NODES + 255) / 256, 256, 0, s1>>>();                 // 3

    // GEMM branch (main): 4th launch -> gets profiled
    const int gemm_blocks = (N_NODES + 63) / 64;                           // 1563
    gemm_kernel<<<gemm_blocks, 256, GEMM_SMEM>>>(h, W, attn);              // 4

    scatter_src_kernel<<<(N_EDGES + 255) / 256, 256, 0, s1>>>(esrc, edst); // 5

    // join: aggregate needs gemm (main) + scatter (s1)
    cudaEventRecord(evJoin, s1);
    cudaStreamWaitEvent(0, evJoin, 0);
    aggregate_kernel<<<(N_NODES * 32 + 255) / 256, 256>>>(out);            // 6
}

// round 16
// speedup vs baseline: 1.0947x; 1.0402x over previous
#include <cuda_runtime.h>
#include <cuda_fp16.h>
#include <mma.h>

using namespace nvcuda;

#define N_NODES 100000
#define N_EDGES 1600000
#define D 128
#define NEG_SLOPE 0.01f

typedef unsigned long long ull;

// ---------------- device scratch ----------------------------------------------
__device__ __half g_zh[N_NODES * D];       // z = h@W, fp16
__device__ float  g_wa[256];               // [W@a1 ; W@a2] (row-dots of W)
__device__ float  g_ssrc[N_NODES];
__device__ float  g_sdst[N_NODES];
__device__ int    g_cnt[N_NODES];          // in-degree histogram (self-cleaning)
__device__ int    g_rank[N_EDGES];         // rank of edge within its dst segment
__device__ int    g_loc[N_NODES];          // block-local exclusive scan
__device__ int    g_part[128];             // per-block totals
__device__ int    g_rowptr[N_NODES + 1];
__device__ int    g_srcs[N_EDGES];         // src ids grouped by dst (score-free)

// ---------------- f32x2 helpers ------------------------------------------------
__device__ __forceinline__ ull ffma2(ull a, ull b, ull c) {
    ull d;
    asm("fma.rn.f32x2 %0, %1, %2, %3;" : "=l"(d) : "l"(a), "l"(b), "l"(c));
    return d;
}
__device__ __forceinline__ ull fadd2(ull a, ull b) {
    ull d;
    asm("add.rn.f32x2 %0, %1, %2;" : "=l"(d) : "l"(a), "l"(b));
    return d;
}
__device__ __forceinline__ ull pack2(float x, float y) {
    ull d;
    asm("mov.b64 %0, {%1, %2};" : "=l"(d) : "f"(x), "f"(y));
    return d;
}
__device__ __forceinline__ float2 unpack2(ull v) {
    float2 r;
    asm("mov.b64 {%0, %1}, %2;" : "=f"(r.x), "=f"(r.y) : "l"(v));
    return r;
}

// ---------------- 0) wproj: wa[k] = W[k,:]@a (1 block, trivial) ---------------
// s_src = (hW)@a1 = h@(W@a1). VERIFIED correct in R13 (rel_err 3.5e-4 pass).
__global__ void wproj_kernel(const float* __restrict__ W,
                             const float* __restrict__ attn) {
    int t = threadIdx.x;                       // 256
    int k = t & 127;                           // W row
    const float* a = attn + ((t >> 7) << 7);   // a1 for t<128, a2 for t>=128
    const float* wr = W + k * D;
    float s = 0.f;
#pragma unroll 8
    for (int c = 0; c < 128; c++)
        s = fmaf(wr[c], a[c], s);
    g_wa[t] = s;
}

// ---------------- 1) GEMM z = h@W via HMMA (M=64) + dots in staging -----------
// Warp grid 2(m)x4(n), warp tile 32x32 = 2x2 wmma frags.
// Dots computed DURING h staging: warp-iter j covers exactly one h row across
// its 32 lanes (fp32, exact). Epilogue = cvt+store only (no attn LDGs).
#define APITCH 136   // half pitch for A/B smem tiles
#define CPITCH 132   // float pitch for C smem tile
#define WA_OFF ((64 + 128) * APITCH * 2)           // 52224
#define GEMM_SMEM (WA_OFF + 256 * 4)               // 53248 B -> 4 blocks/SM

__global__ void gemm_kernel(const float* __restrict__ h, const float* __restrict__ W) {
    extern __shared__ char smem[];
    __half* As  = (__half*)smem;                      // [64][APITCH]  (h tile)
    __half* Bs  = (__half*)(smem + 64 * APITCH * 2);  // [128][APITCH] (W)
    float*  Cs  = (float*)smem;                       // [64][CPITCH] overlay
    float*  was = (float*)(smem + WA_OFF);            // wa[256]

    const int tid  = threadIdx.x;                     // 256 threads
    const int lane = tid & 31;
    const int row0 = blockIdx.x * 64;

    // stage wa (1 float/thread) + W -> fp16 smem
    was[tid] = g_wa[tid];
    for (int i = tid; i < 128 * 32; i += 256) {
        int k = i >> 5, c4 = i & 31;
        float4 v = *(const float4*)(W + k * D + c4 * 4);
        __half2 h0 = __floats2half2_rn(v.x, v.y);
        __half2 h1 = __floats2half2_rn(v.z, v.w);
        uint2 u;
        u.x = *(unsigned*)&h0;
        u.y = *(unsigned*)&h1;
        *(uint2*)(Bs + k * APITCH + c4 * 4) = u;
    }
    __syncthreads();   // was visible before h-staging dots

    // stage h tile -> fp16 smem, computing s_src/s_dst on the fly.
    // iter j: warp w covers row 8j + w entirely (lane = k-quad).
#pragma unroll
    for (int j = 0; j < 8; j++) {
        int i = tid + j * 256;
        int r = i >> 5, kq = i & 31;
        int row = row0 + r;
        float4 v = make_float4(0.f, 0.f, 0.f, 0.f);
        if (row < N_NODES) v = *(const float4*)(h + (size_t)row * D + kq * 4);
        __half2 h0 = __floats2half2_rn(v.x, v.y);
        __half2 h1 = __floats2half2_rn(v.z, v.w);
        uint2 u;
        u.x = *(unsigned*)&h0;
        u.y = *(unsigned*)&h1;
        *(uint2*)(As + r * APITCH + kq * 4) = u;

        float4 w1 = *(const float4*)(was + kq * 4);
        float4 w2 = *(const float4*)(was + 128 + kq * 4);
        float p = v.x * w1.x + v.y * w1.y + v.z * w1.z + v.w * w1.w;
        float q = v.x * w2.x + v.y * w2.y + v.z * w2.z + v.w * w2.w;
#pragma unroll
        for (int off = 16; off; off >>= 1) {
            p += __shfl_xor_sync(0xffffffffu, p, off);
            q += __shfl_xor_sync(0xffffffffu, q, off);
        }
        if (lane == 0 && row < N_NODES) {
            g_ssrc[row] = p;
            g_sdst[row] = q;
        }
    }
    __syncthreads();

    const int warp = tid >> 5;      // 0..7
    const int wm = warp & 1;        // rows wm*32
    const int wn = warp >> 1;       // cols wn*32

    wmma::fragment<wmma::accumulator, 16, 16, 16, float> acc[2][2];
#pragma unroll
    for (int i = 0; i < 2; i++)
#pragma unroll
        for (int j = 0; j < 2; j++) wmma::fill_fragment(acc[i][j], 0.f);

#pragma unroll
    for (int k0 = 0; k0 < 8; k0++) {
        wmma::fragment<wmma::matrix_a, 16, 16, 16, __half, wmma::row_major> af[2];
        wmma::fragment<wmma::matrix_b, 16, 16, 16, __half, wmma::row_major> bf[2];
#pragma unroll
        for (int i = 0; i < 2; i++)
            wmma::load_matrix_sync(af[i], As + (wm * 32 + i * 16) * APITCH + k0 * 16, APITCH);
#pragma unroll
        for (int j = 0; j < 2; j++)
            wmma::load_matrix_sync(bf[j], Bs + (k0 * 16) * APITCH + wn * 32 + j * 16, APITCH);
#pragma unroll
        for (int i = 0; i < 2; i++)
#pragma unroll
            for (int j = 0; j < 2; j++)
                wmma::mma_sync(acc[i][j], af[i], bf[j], acc[i][j]);
    }

    __syncthreads();   // done reading As/Bs; reuse smem as Cs
#pragma unroll
    for (int i = 0; i < 2; i++)
#pragma unroll
        for (int j = 0; j < 2; j++)
            wmma::store_matrix_sync(Cs + (wm * 32 + i * 16) * CPITCH + wn * 32 + j * 16,
                                    acc[i][j], CPITCH, wmma::mem_row_major);
    __syncthreads();

    // epilogue: 4 threads/row, 32 cols each; cvt + fp16 z store only
    {
        int r    = tid >> 2;          // 0..63
        int part = tid & 3;
        int c0   = part * 32;
        int row  = row0 + r;
        if (row < N_NODES) {
            const float* crow = Cs + r * CPITCH + c0;
            __half* zrow = g_zh + (size_t)row * D + c0;
#pragma unroll
            for (int c = 0; c < 32; c += 4) {
                float4 v = *(const float4*)(crow + c);
                __half2 h0 = __floats2half2_rn(v.x, v.y);
                __half2 h1 = __floats2half2_rn(v.z, v.w);
                uint2 u;
                u.x = *(unsigned*)&h0;
                u.y = *(unsigned*)&h1;
                *(uint2*)(zrow + c) = u;
            }
        }
    }
}

// ---------------- 2) CSR build + score-free scatter (runs fully || GEMM) ------
__global__ void hist_kernel(const int* __restrict__ edst) {
    int i = blockIdx.x * blockDim.x + threadIdx.x;
    if (i < N_EDGES) g_rank[i] = atomicAdd(&g_cnt[edst[i]], 1);
}

__global__ void scanA_kernel() {   // 98 blocks x 1024, shfl-based
    __shared__ int wsum[32];
    int t = threadIdx.x, lane = t & 31, w = t >> 5;
    int i = blockIdx.x * 1024 + t;
    int v = (i < N_NODES) ? g_cnt[i] : 0;
    int x = v;
#pragma unroll
    for (int off = 1; off < 32; off <<= 1) {
        int y = __shfl_up_sync(0xffffffffu, x, off);
        if (lane >= off) x += y;
    }
    if (lane == 31) wsum[w] = x;
    __syncthreads();
    if (t < 32) {
        int tot = wsum[t];
        int xs = tot;
#pragma unroll
        for (int off = 1; off < 32; off <<= 1) {
            int y = __shfl_up_sync(0xffffffffu, xs, off);
            if (t >= off) xs += y;
        }
        wsum[t] = xs - tot;
        if (t == 31) g_part[blockIdx.x] = xs;
    }
    __syncthreads();
    if (i < N_NODES) g_loc[i] = x + wsum[w] - v;
}

// merged scanB+scanC: each block redundantly scans the 98 partials, emits rowptr,
// and re-zeroes g_cnt (self-cleaning for graph replay).
__global__ void scanC_kernel() {
    __shared__ int s[128];
    const int NB = (N_NODES + 1023) / 1024;
    int t = threadIdx.x;            // 256 threads
    if (t < 128) {
        int v = (t < NB) ? g_part[t] : 0;
        s[t] = v;
    }
    __syncthreads();
#pragma unroll
    for (int off = 1; off < 128; off <<= 1) {
        int tmp = 0;
        if (t < 128 && t >= off) tmp = s[t - off];
        __syncthreads();
        if (t < 128) s[t] += tmp;
        __syncthreads();
    }
    int i = blockIdx.x * blockDim.x + t;
    if (i < N_NODES) {
        int b = i >> 10;
        int poff = s[b] - ((b < NB) ? g_part[b] : 0);
        g_rowptr[i] = g_loc[i] + poff;
        g_cnt[i] = 0;
    }
    if (i == 0) g_rowptr[N_NODES] = N_EDGES;
}

// scatter src ids only — no GEMM/score dependency, lives in the parallel branch
__global__ void scatter_src_kernel(const int* __restrict__ esrc,
                                   const int* __restrict__ edst) {
    int i = blockIdx.x * blockDim.x + threadIdx.x;
    if (i < N_EDGES) {
        int d = edst[i];
        g_srcs[g_rowptr[d] + g_rank[i]] = esrc[i];
    }
}

// ---------------- 3) aggregate: warp/node, inline exp, pair-gather ------------
// Softmax without max-shift is exact here (|score| < ~8, exp cannot overflow).
// lanes 0-15 carry edge j's z-row half (16B/lane), lanes 16-31 edge j+1's.
__device__ __forceinline__ void acc_pair(int jj, float wgt, int s, int qoff,
                                         ull& a0, ull& a1, ull& a2, ull& a3) {
    float wj = __shfl_sync(0xffffffffu, wgt, jj);
    int   sj = __shfl_sync(0xffffffffu, s, jj);
    uint4 u = *(const uint4*)(g_zh + (size_t)sj * D + qoff);
    ull wd = pack2(wj, wj);
    float2 f;
    f = __half22float2(*(__half2*)&u.x); a0 = ffma2(pack2(f.x, f.y), wd, a0);
    f = __half22float2(*(__half2*)&u.y); a1 = ffma2(pack2(f.x, f.y), wd, a1);
    f = __half22float2(*(__half2*)&u.z); a2 = ffma2(pack2(f.x, f.y), wd, a2);
    f = __half22float2(*(__half2*)&u.w); a3 = ffma2(pack2(f.x, f.y), wd, a3);
}

__global__ void aggregate_kernel(float* __restrict__ out) {
    int gw   = (blockIdx.x * blockDim.x + threadIdx.x) >> 5;
    int lane = threadIdx.x & 31;
    if (gw >= N_NODES) return;

    int q  = lane & 15;           // column group: cols 8q..8q+7
    int hi = lane >> 4;           // even/odd edge of pair
    int qoff = q * 8;

    int beg = g_rowptr[gw];
    int end = g_rowptr[gw + 1];
    float* owr = out + (size_t)gw * D + qoff + hi * 4;

    if (beg == end) {
        *(float4*)owr = make_float4(0.f, 0.f, 0.f, 0.f);
        return;
    }

    float sd = g_sdst[gw];
    ull a0 = 0ull, a1 = 0ull, a2 = 0ull, a3 = 0ull;
    float denom = 0.f;

    for (int base = beg; base < end; base += 32) {
        int   i = base + lane;
        int   s = 0;
        float wgt = 0.f;
        if (i < end) {
            s = g_srcs[i];                // coalesced LDG.32
            float e = g_ssrc[s] + sd;     // random 4B gather, L2-resident
            e = (e > 0.f) ? e : NEG_SLOPE * e;
            wgt = __expf(e);
        }
        denom += wgt;
        int cnt = end - base;
        if (cnt > 32) cnt = 32;

        int j = 0;
        for (; j + 8 <= cnt; j += 8) {
            int   jj0 = j + 0 + hi, jj1 = j + 2 + hi, jj2 = j + 4 + hi, jj3 = j + 6 + hi;
            float w0 = __shfl_sync(0xffffffffu, wgt, jj0);
            float w1 = __shfl_sync(0xffffffffu, wgt, jj1);
            float w2 = __shfl_sync(0xffffffffu, wgt, jj2);
            float w3 = __shfl_sync(0xffffffffu, wgt, jj3);
            int   s0 = __shfl_sync(0xffffffffu, s, jj0);
            int   s1 = __shfl_sync(0xffffffffu, s, jj1);
            int   s2 = __shfl_sync(0xffffffffu, s, jj2);
            int   s3 = __shfl_sync(0xffffffffu, s, jj3);
            uint4 u0 = *(const uint4*)(g_zh + (size_t)s0 * D + qoff);
            uint4 u1 = *(const uint4*)(g_zh + (size_t)s1 * D + qoff);
            uint4 u2 = *(const uint4*)(g_zh + (size_t)s2 * D + qoff);
            uint4 u3 = *(const uint4*)(g_zh + (size_t)s3 * D + qoff);
            ull wd; float2 f;
            wd = pack2(w0, w0);
            f = __half22float2(*(__half2*)&u0.x); a0 = ffma2(pack2(f.x, f.y), wd, a0);
            f = __half22float2(*(__half2*)&u0.y); a1 = ffma2(pack2(f.x, f.y), wd, a1);
            f = __half22float2(*(__half2*)&u0.z); a2 = ffma2(pack2(f.x, f.y), wd, a2);
            f = __half22float2(*(__half2*)&u0.w); a3 = ffma2(pack2(f.x, f.y), wd, a3);
            wd = pack2(w1, w1);
            f = __half22float2(*(__half2*)&u1.x); a0 = ffma2(pack2(f.x, f.y), wd, a0);
            f = __half22float2(*(__half2*)&u1.y); a1 = ffma2(pack2(f.x, f.y), wd, a1);
            f = __half22float2(*(__half2*)&u1.z); a2 = ffma2(pack2(f.x, f.y), wd, a2);
            f = __half22float2(*(__half2*)&u1.w); a3 = ffma2(pack2(f.x, f.y), wd, a3);
            wd = pack2(w2, w2);
            f = __half22float2(*(__half2*)&u2.x); a0 = ffma2(pack2(f.x, f.y), wd, a0);
            f = __half22float2(*(__half2*)&u2.y); a1 = ffma2(pack2(f.x, f.y), wd, a1);
            f = __half22float2(*(__half2*)&u2.z); a2 = ffma2(pack2(f.x, f.y), wd, a2);
            f = __half22float2(*(__half2*)&u2.w); a3 = ffma2(pack2(f.x, f.y), wd, a3);
            wd = pack2(w3, w3);
            f = __half22float2(*(__half2*)&u3.x); a0 = ffma2(pack2(f.x, f.y), wd, a0);
            f = __half22float2(*(__half2*)&u3.y); a1 = ffma2(pack2(f.x, f.y), wd, a1);
            f = __half22float2(*(__half2*)&u3.z); a2 = ffma2(pack2(f.x, f.y), wd, a2);
            f = __half22float2(*(__half2*)&u3.w); a3 = ffma2(pack2(f.x, f.y), wd, a3);
        }
        for (; j < cnt; j += 2)
            acc_pair(j + hi, wgt, s, qoff, a0, a1, a2, a3);
    }

    a0 = fadd2(a0, __shfl_xor_sync(0xffffffffu, a0, 16));
    a1 = fadd2(a1, __shfl_xor_sync(0xffffffffu, a1, 16));
    a2 = fadd2(a2, __shfl_xor_sync(0xffffffffu, a2, 16));
    a3 = fadd2(a3, __shfl_xor_sync(0xffffffffu, a3, 16));
#pragma unroll
    for (int off = 16; off; off >>= 1)
        denom += __shfl_xor_sync(0xffffffffu, denom, off);

    float inv = 1.f / denom;
    float2 r0 = unpack2(a0), r1 = unpack2(a1), r2 = unpack2(a2), r3 = unpack2(a3);
    float4 res = hi ? make_float4(r2.x * inv, r2.y * inv, r3.x * inv, r3.y * inv)
                    : make_float4(r0.x * inv, r0.y * inv, r1.x * inv, r1.y * inv);
    *(float4*)owr = res;
}

// ---------------- launch: 2-stream fork-join, tail = aggregate only -----------
extern "C" void kernel_launch(void* const* d_in, const int* in_sizes, int n_in,
                              void* d_out, int out_size) {
    const float* h    = (const float*)d_in[0];
    const float* W    = (const float*)d_in[1];
    const float* attn = (const float*)d_in[2];
    const int*   esrc = (const int*)d_in[3];
    const int*   edst = (const int*)d_in[4];
    float*       out  = (float*)d_out;

    static cudaStream_t s1 = nullptr;
    static cudaEvent_t  evFork = nullptr, evJoin = nullptr;
    if (s1 == nullptr) {   // first call is the uncaptured correctness run
        cudaStreamCreateWithFlags(&s1, cudaStreamNonBlocking);
        cudaEventCreateWithFlags(&evFork, cudaEventDisableTiming);
        cudaEventCreateWithFlags(&evJoin, cudaEventDisableTiming);
        cudaFuncSetAttribute(gemm_kernel,
                             cudaFuncAttributeMaxDynamicSharedMemorySize, GEMM_SMEM);
    }

    // fork
    cudaEventRecord(evFork, 0);
    cudaStreamWaitEvent(s1, evFork, 0);

    // launch order: gemm is 4th (profiler window)
    wproj_kernel<<<1, 256>>>(W, attn);                                     // 1 (main)
    hist_kernel<<<(N_EDGES + 255) / 256, 256, 0, s1>>>(edst);              // 2 (s1)
    scanA_kernel<<<(N_NODES + 1023) / 1024, 1024, 0, s1>>>();              // 3 (s1)
    const int gemm_blocks = (N_NODES + 63) / 64;                           // 1563
    gemm_kernel<<<gemm_blocks, 256, GEMM_SMEM>>>(h, W);                    // 4 (main)
    scanC_kernel<<<(N_NODES + 255) / 256, 256, 0, s1>>>();                 // 5 (s1)
    scatter_src_kernel<<<(N_EDGES + 255) / 256, 256, 0, s1>>>(esrc, edst); // 6 (s1)

    // join: aggregate needs gemm (main) + scatter (s1)
    cudaEventRecord(evJoin, s1);
    cudaStreamWaitEvent(0, evJoin, 0);
    aggregate_kernel<<<(N_NODES * 32 + 255) / 256, 256>>>(out);            // 7
}